// round 15
// baseline (speedup 1.0000x reference)
#include <cuda_runtime.h>
#include <math.h>
#include <stdint.h>

#define Bc   4
#define Gc   16906
#define Nc   16907
#define Dc   256
#define Hc   8
#define DHc  32
#define Mc   110
#define Lc   6
#define FFc  1024
#define Sc   8
#define Rc   (Bc*Sc)           // 32 state rows
#define NB   64                // persistent blocks
#define NT   256

#define XN_SCALE   0.42044820762685725f   // 32^-0.25
#define M_RSQRT    0.09534625892455922f   // 110^-0.5
#define FEPS       1e-4f

// ---------------- device scratch ----------------
__device__ __align__(128) float g_e[Bc*Gc];
__device__ float    g_rowsum[Bc];
__device__ unsigned g_umax;
__device__ unsigned g_ustab[Lc];
__device__ int      g_cnt[Rc];
__device__ __align__(128) float g_sx[Rc*Dc];
__device__ __align__(128) float g_sh[Rc*Dc];
__device__ __align__(128) float g_sq[Rc*Dc];
__device__ __align__(128) float g_sk[Rc*Dc];
__device__ __align__(128) float g_sv[Rc*Dc];
__device__ __align__(128) float g_so[Rc*Dc];
__device__ __align__(128) float g_sff[Rc*FFc];
__device__ int          g_bar_count = 0;
__device__ volatile int g_bar_gen   = 0;

__device__ __forceinline__ unsigned fflip(float f){
    unsigned u = __float_as_uint(f);
    return (u & 0x80000000u) ? ~u : (u | 0x80000000u);
}
__device__ __forceinline__ float funflip(unsigned u){
    unsigned b = (u & 0x80000000u) ? (u ^ 0x80000000u) : ~u;
    return __uint_as_float(b);
}
__device__ __forceinline__ float gelu_exact(float x){
    return 0.5f*x*(1.0f + erff(x*0.7071067811865476f));
}

__device__ __forceinline__ void gridbar(){
    __syncthreads();
    if(threadIdx.x==0){
        int gen = g_bar_gen;
        __threadfence();
        if(atomicAdd(&g_bar_count, 1) == NB-1){
            g_bar_count = 0;
            __threadfence();
            g_bar_gen = gen + 1;
        } else {
            while(g_bar_gen == gen) { }
        }
    }
    __syncthreads();
}

// GEMV over 32 state rows: Y[r][c] = act(X[r][:] . W[:,c] + bias[c])
// mode: 0 plain ; 1 +residual(Y in-place ok) ; 2 gelu
__device__ __forceinline__ void gemv_stage(const float* __restrict__ X, const float* __restrict__ W,
                                           const float* __restrict__ bias, const float* __restrict__ Rres,
                                           float* __restrict__ Y, int K, int N, int mode){
    int total = Rc*N;
    for(int idx = blockIdx.x*NT + threadIdx.x; idx < total; idx += NB*NT){
        int r = idx / N, c = idx - r*N;
        const float* xp = X + (size_t)r*K;
        const float* wp = W + c;
        float a = 0.f;
        #pragma unroll 16
        for(int k=0;k<K;k++) a += xp[k]*wp[(size_t)k*N];
        a += bias[c];
        if(mode==1) a += Rres[idx];
        if(mode==2) a = gelu_exact(a);
        Y[idx] = a;
    }
}

// LayerNorm over 32 rows: blocks 0..31, one row each
__device__ __forceinline__ void ln_stage(const float* __restrict__ X, const float* __restrict__ gw,
                                         const float* __restrict__ bw, float* __restrict__ Y,
                                         float* sred){
    if(blockIdx.x >= Rc) return;
    int r = blockIdx.x, tid = threadIdx.x;
    float v = X[(size_t)r*Dc + tid];
    sred[tid] = v; __syncthreads();
    for(int st=128; st; st>>=1){ if(tid<st) sred[tid]+=sred[tid+st]; __syncthreads(); }
    float mu = sred[0]*(1.f/256.f);
    __syncthreads();
    float d = v - mu;
    sred[tid] = d*d; __syncthreads();
    for(int st=128; st; st>>=1){ if(tid<st) sred[tid]+=sred[tid+st]; __syncthreads(); }
    float rstd = rsqrtf(sred[0]*(1.f/256.f) + 1e-5f);
    __syncthreads();
    Y[(size_t)r*Dc + tid] = d*rstd*gw[tid] + bw[tid];
}

__global__ __launch_bounds__(NT)
void forward_kernel(const float* __restrict__ expr, const float* __restrict__ temb,
                    const float* __restrict__ cls,
                    const float* __restrict__ ln1_g, const float* __restrict__ ln1_b,
                    const float* __restrict__ wq, const float* __restrict__ bq,
                    const float* __restrict__ wk, const float* __restrict__ bk,
                    const float* __restrict__ wv, const float* __restrict__ bv,
                    const float* __restrict__ wo, const float* __restrict__ bo,
                    const float* __restrict__ ln2_g, const float* __restrict__ ln2_b,
                    const float* __restrict__ w1, const float* __restrict__ b1,
                    const float* __restrict__ w2, const float* __restrict__ b2,
                    const float* __restrict__ pw, const float* __restrict__ pb,
                    const float* __restrict__ projs,
                    float* __restrict__ out)
{
    __shared__ float sred[NT];
    __shared__ int   shist[Sc];
    // attention smem
    __shared__ float sp[Mc*DHc];
    __shared__ float xk[Sc][DHc], xq[Sc][DHc], xv[Sc][DHc];
    __shared__ float kf[Sc][112], qf[Sc][112];
    __shared__ float sctx[Mc*DHc];
    __shared__ float sksum[112];
    __shared__ float sden[Sc], dgk[Sc], dgq[Sc], scnt[Sc];

    const int tid = threadIdx.x;
    const int bid = blockIdx.x;
    const int gidx0 = bid*NT + tid;

    // ---------- S0: reset + rowsum ----------
    if(bid == 0 && tid == 0){
        g_umax = 0u;
        for(int l=0;l<Lc;l++) g_ustab[l] = 0u;
    }
    if(bid < NB && gidx0 < Rc + NB*NT){ /* no-op shape */ }
    for(int i = gidx0; i < Rc; i += NB*NT) g_cnt[i] = ((i&7)==7) ? 1 : 0;
    if(bid < Bc){
        int b = bid;
        float s = 0.f;
        for(int i=tid; i<Gc; i+=NT) s += fabsf(expr[(size_t)b*Gc+i]);
        sred[tid]=s; __syncthreads();
        for(int st=128; st; st>>=1){ if(tid<st) sred[tid]+=sred[tid+st]; __syncthreads(); }
        if(tid==0) g_rowsum[b]=sred[0];
    }
    gridbar();

    // ---------- S1: e = log1p(...), global max ----------
    {
        float lmax = 0.f;
        for(int i = gidx0; i < Bc*Gc; i += NB*NT){
            int b = i / Gc;
            float denom = fmaxf(g_rowsum[b], 1e-12f);
            float e = log1pf(expr[i]/denom*1e4f);
            g_e[i] = e;
            lmax = fmaxf(lmax, e);
        }
        sred[tid]=lmax; __syncthreads();
        for(int st=128; st; st>>=1){ if(tid<st) sred[tid]=fmaxf(sred[tid],sred[tid+st]); __syncthreads(); }
        if(tid==0) atomicMax(&g_umax, fflip(sred[0]));
    }
    gridbar();

    // ---------- S2: histogram (smem-local) + seed states ----------
    {
        if(tid < 2*Sc) ((int*)shist)[tid & (2*Sc-1)] = 0;   // zero 8 per-batch... use full 32
    }
    __shared__ int shist32[Rc];
    if(tid < Rc) shist32[tid] = 0;
    __syncthreads();
    {
        float maxe = funflip(g_umax);
        float step = maxe/7.0f;
        for(int i = gidx0; i < Bc*Gc; i += NB*NT){
            int b = i / Gc;
            float e = g_e[i];
            int t = (0.0f < e) ? 1 : 0;
            #pragma unroll
            for(int j=1;j<7;j++) t += ((float)j*step < e) ? 1 : 0;
            if(t>6) t=6;
            atomicAdd(&shist32[b*8+t], 1);
        }
    }
    __syncthreads();
    if(tid < Rc && shist32[tid] != 0) atomicAdd(&g_cnt[tid], shist32[tid]);
    // seed 32 state rows
    for(int i = gidx0; i < Rc*Dc; i += NB*NT){
        int r = i >> 8, d = i & 255;
        int s = r & 7;
        g_sx[i] = (s==7) ? cls[d] : temb[s*Dc + d];
    }
    gridbar();

    // ---------- layers ----------
    for(int l=0; l<Lc; l++){
        const float* wq_l = wq + (size_t)l*Dc*Dc;  const float* bq_l = bq + l*Dc;
        const float* wk_l = wk + (size_t)l*Dc*Dc;  const float* bk_l = bk + l*Dc;
        const float* wv_l = wv + (size_t)l*Dc*Dc;  const float* bv_l = bv + l*Dc;
        const float* wo_l = wo + (size_t)l*Dc*Dc;  const float* bo_l = bo + l*Dc;
        const float* w1_l = w1 + (size_t)l*Dc*FFc; const float* b1_l = b1 + l*FFc;
        const float* w2_l = w2 + (size_t)l*FFc*Dc; const float* b2_l = b2 + l*Dc;
        const float* pr_l = projs + (size_t)l*Mc*DHc;

        ln_stage(g_sx, ln1_g + l*Dc, ln1_b + l*Dc, g_sh, sred);
        gridbar();

        gemv_stage(g_sh, wq_l, bq_l, nullptr, g_sq, Dc, Dc, 0);
        gemv_stage(g_sh, wk_l, bk_l, nullptr, g_sk, Dc, Dc, 0);
        gemv_stage(g_sh, wv_l, bv_l, nullptr, g_sv, Dc, Dc, 0);
        gridbar();

        // stabilizer: blocks 0..31, bh each
        if(bid < Rc){
            int b = bid>>3, h = bid&7;
            for(int i=tid;i<Mc*DHc;i+=NT) sp[i]=pr_l[i];
            { int s=tid>>5, d=tid&31; xk[s][d]=g_sk[(size_t)(b*8+s)*Dc + h*DHc + d]*XN_SCALE; }
            __syncthreads();
            float mx = -3.4e38f;
            for(int i=tid;i<Sc*Mc;i+=NT){
                int s=i/Mc, m=i%Mc;
                if(g_cnt[b*8+s] > 0){
                    float dd=0.f;
                    #pragma unroll
                    for(int d=0;d<DHc;d++) dd += xk[s][d]*sp[m*DHc+d];
                    mx = fmaxf(mx, dd);
                }
            }
            sred[tid]=mx; __syncthreads();
            for(int st=128; st; st>>=1){ if(tid<st) sred[tid]=fmaxf(sred[tid],sred[tid+st]); __syncthreads(); }
            if(tid==0) atomicMax(&g_ustab[l], fflip(sred[0]));
        }
        gridbar();

        // attention: blocks 0..31
        if(bid < Rc){
            int b = bid>>3, h = bid&7;
            int warp = tid>>5, lane = tid&31;
            for(int i=tid;i<Mc*DHc;i+=NT) sp[i]=pr_l[i];
            { int s=tid>>5, d=tid&31;
              size_t off = (size_t)(b*8+s)*Dc + h*DHc + d;
              xk[s][d]=g_sk[off]*XN_SCALE;
              xq[s][d]=g_sq[off]*XN_SCALE;
              xv[s][d]=g_sv[off]; }
            if(tid<Sc) scnt[tid] = (float)g_cnt[b*8+tid];
            __syncthreads();
            {
                float kk = xk[warp][lane]*xk[warp][lane];
                float qq = xq[warp][lane]*xq[warp][lane];
                #pragma unroll
                for(int o=16;o;o>>=1){ kk += __shfl_xor_sync(0xffffffffu,kk,o); qq += __shfl_xor_sync(0xffffffffu,qq,o); }
                if(lane==0){ dgk[warp]=0.5f*kk; dgq[warp]=0.5f*qq; }
            }
            __syncthreads();
            float stab = funflip(g_ustab[l]);
            for(int i=tid;i<Sc*Mc;i+=NT){
                int s=i/Mc, m=i%Mc;
                float ddk=0.f, ddq=0.f;
                #pragma unroll
                for(int d=0;d<DHc;d++){ ddk += xk[s][d]*sp[m*DHc+d]; ddq += xq[s][d]*sp[m*DHc+d]; }
                kf[s][m] = M_RSQRT*(expf(ddk - dgk[s] - stab) + FEPS);
                qf[s][m] = ddq;
            }
            __syncthreads();
            {
                float mx=-3.4e38f;
                for(int m=lane;m<Mc;m+=32) mx=fmaxf(mx, qf[warp][m]);
                #pragma unroll
                for(int o=16;o;o>>=1) mx=fmaxf(mx,__shfl_xor_sync(0xffffffffu,mx,o));
                for(int m=lane;m<Mc;m+=32)
                    qf[warp][m] = M_RSQRT*(expf(qf[warp][m]-dgq[warp]-mx) + FEPS);
            }
            __syncthreads();
            for(int i=tid;i<Mc*DHc;i+=NT){
                int m=i>>5, d=i&31;
                float a=0.f;
                #pragma unroll
                for(int s=0;s<Sc;s++) a += scnt[s]*kf[s][m]*xv[s][d];
                sctx[i]=a;
            }
            for(int m=tid;m<Mc;m+=NT){
                float a=0.f;
                #pragma unroll
                for(int s=0;s<Sc;s++) a += scnt[s]*kf[s][m];
                sksum[m]=a;
            }
            __syncthreads();
            {
                float a=0.f;
                for(int m=lane;m<Mc;m+=32) a += qf[warp][m]*sksum[m];
                #pragma unroll
                for(int o=16;o;o>>=1) a += __shfl_xor_sync(0xffffffffu,a,o);
                if(lane==0) sden[warp]=a;
            }
            __syncthreads();
            {
                int s=tid>>5, d=tid&31;
                float a=0.f;
                for(int m=0;m<Mc;m++) a += qf[s][m]*sctx[m*DHc+d];
                g_so[(size_t)(b*8+s)*Dc + h*DHc + d] = a/sden[s];
            }
        }
        gridbar();

        gemv_stage(g_so, wo_l, bo_l, g_sx, g_sx, Dc, Dc, 1);
        gridbar();

        ln_stage(g_sx, ln2_g + l*Dc, ln2_b + l*Dc, g_sh, sred);
        gridbar();

        gemv_stage(g_sh, w1_l, b1_l, nullptr, g_sff, Dc, FFc, 2);
        gridbar();

        gemv_stage(g_sff, w2_l, b2_l, g_sx, g_sx, FFc, Dc, 1);
        gridbar();
    }

    // ---------- final projection (cls rows) ----------
    for(int idx = gidx0; idx < Bc*Dc; idx += NB*NT){
        int b = idx >> 8, j = idx & 255;
        const float* xp = g_sx + (size_t)(b*8+7)*Dc;
        float a=0.f;
        #pragma unroll 16
        for(int d=0;d<Dc;d++) a += xp[d]*pw[(size_t)d*Dc+j];
        out[idx] = a + pb[j];
    }
}

// ---------------- launch ----------------
extern "C" void kernel_launch(void* const* d_in, const int* in_sizes, int n_in,
                              void* d_out, int out_size){
    const float* expr      = (const float*)d_in[0];
    const float* token_emb = (const float*)d_in[1];
    const float* cls_token = (const float*)d_in[2];
    const float* ln1_g     = (const float*)d_in[3];
    const float* ln1_b     = (const float*)d_in[4];
    const float* wq        = (const float*)d_in[5];
    const float* bq        = (const float*)d_in[6];
    const float* wk        = (const float*)d_in[7];
    const float* bk        = (const float*)d_in[8];
    const float* wv        = (const float*)d_in[9];
    const float* bv        = (const float*)d_in[10];
    const float* wo        = (const float*)d_in[11];
    const float* bo        = (const float*)d_in[12];
    const float* ln2_g     = (const float*)d_in[13];
    const float* ln2_b     = (const float*)d_in[14];
    const float* w1        = (const float*)d_in[15];
    const float* b1        = (const float*)d_in[16];
    const float* w2        = (const float*)d_in[17];
    const float* b2        = (const float*)d_in[18];
    const float* proj_w    = (const float*)d_in[19];
    const float* proj_b    = (const float*)d_in[20];
    const float* projs     = (const float*)d_in[21];
    float* out = (float*)d_out;

    forward_kernel<<<NB, NT>>>(expr, token_emb, cls_token,
                               ln1_g, ln1_b, wq, bq, wk, bk, wv, bv, wo, bo,
                               ln2_g, ln2_b, w1, b1, w2, b2,
                               proj_w, proj_b, projs, out);
}

// round 16
// speedup vs baseline: 1.3340x; 1.3340x over previous
#include <cuda_runtime.h>
#include <math.h>
#include <stdint.h>

#define Bc   4
#define Gc   16906
#define Nc   16907
#define Dc   256
#define Hc   8
#define DHc  32
#define Mc   110
#define Lc   6
#define FFc  1024
#define Sc   8
#define Rc   (Bc*Sc)           // 32 state rows
#define NB   64                // persistent blocks
#define NT   256

#define XN_SCALE   0.42044820762685725f   // 32^-0.25
#define M_RSQRT    0.09534625892455922f   // 110^-0.5
#define FEPS       1e-4f

// ---------------- device scratch ----------------
__device__ __align__(128) float g_e[Bc*Gc];
__device__ float    g_part[Bc*16];
__device__ unsigned g_umax;
__device__ unsigned g_ustab[Lc];
__device__ int      g_cnt[Rc];
__device__ __align__(128) float g_sx[Rc*Dc];
__device__ __align__(128) float g_sq[Rc*Dc];
__device__ __align__(128) float g_sk[Rc*Dc];
__device__ __align__(128) float g_sv[Rc*Dc];
__device__ __align__(128) float g_so[Rc*Dc];
__device__ __align__(128) float g_sff[Rc*FFc];
__device__ int          g_bar_count = 0;
__device__ volatile int g_bar_gen   = 0;

__device__ __forceinline__ unsigned fflip(float f){
    unsigned u = __float_as_uint(f);
    return (u & 0x80000000u) ? ~u : (u | 0x80000000u);
}
__device__ __forceinline__ float funflip(unsigned u){
    unsigned b = (u & 0x80000000u) ? (u ^ 0x80000000u) : ~u;
    return __uint_as_float(b);
}
__device__ __forceinline__ float gelu_exact(float x){
    return 0.5f*x*(1.0f + erff(x*0.7071067811865476f));
}

__device__ __forceinline__ void gridbar(){
    __syncthreads();
    if(threadIdx.x==0){
        int gen = g_bar_gen;
        __threadfence();
        if(atomicAdd(&g_bar_count, 1) == NB-1){
            g_bar_count = 0;
            __threadfence();
            g_bar_gen = gen + 1;
        } else {
            while(g_bar_gen == gen) { }
            __threadfence();
        }
    }
    __syncthreads();
}

__global__ __launch_bounds__(NT)
void forward_kernel(const float* __restrict__ expr, const float* __restrict__ temb,
                    const float* __restrict__ cls,
                    const float* __restrict__ ln1_g, const float* __restrict__ ln1_b,
                    const float* __restrict__ wq, const float* __restrict__ bq,
                    const float* __restrict__ wk, const float* __restrict__ bk,
                    const float* __restrict__ wv, const float* __restrict__ bv,
                    const float* __restrict__ wo, const float* __restrict__ bo,
                    const float* __restrict__ ln2_g, const float* __restrict__ ln2_b,
                    const float* __restrict__ w1, const float* __restrict__ b1,
                    const float* __restrict__ w2, const float* __restrict__ b2,
                    const float* __restrict__ pw, const float* __restrict__ pb,
                    const float* __restrict__ projs,
                    float* __restrict__ out)
{
    __shared__ float sred[NT];
    __shared__ float srow[FFc];          // row buffer (up to 1024)
    __shared__ int   shist32[Rc];
    // attention smem (persists across the mid-attention grid barrier)
    __shared__ float sp[Mc*DHc];
    __shared__ float xk[Sc][DHc], xq[Sc][DHc], xv[Sc][DHc];
    __shared__ float kf[Sc][112], qf[Sc][112];
    __shared__ float sctx[Mc*DHc];
    __shared__ float sksum[112];
    __shared__ float sden[Sc], dgk[Sc], dgq[Sc], scnt[Sc];

    const int tid = threadIdx.x;
    const int bid = blockIdx.x;
    const int gidx0 = bid*NT + tid;
    const int warp = tid>>5, lane = tid&31;

    // ---------- S0: reset + partial rowsums (64 blocks: b = bid>>4, slice = bid&15) ----------
    if(bid == 0 && tid == 0){
        g_umax = 0u;
        for(int l=0;l<Lc;l++) g_ustab[l] = 0u;
    }
    for(int i = gidx0; i < Rc; i += NB*NT) g_cnt[i] = ((i&7)==7) ? 1 : 0;
    {
        int b = bid>>4, slice = bid&15;
        int start = slice*1057;
        int end = start+1057 < Gc ? start+1057 : Gc;
        float s = 0.f;
        for(int i=start+tid; i<end; i+=NT) s += fabsf(expr[(size_t)b*Gc+i]);
        sred[tid]=s; __syncthreads();
        for(int st=128; st; st>>=1){ if(tid<st) sred[tid]+=sred[tid+st]; __syncthreads(); }
        if(tid==0) g_part[b*16+slice]=sred[0];
    }
    gridbar();

    // ---------- S1: e + global max ----------
    {
        float den[Bc];
        #pragma unroll
        for(int b=0;b<Bc;b++){
            float s=0.f;
            #pragma unroll
            for(int j=0;j<16;j++) s += g_part[b*16+j];
            den[b] = fmaxf(s, 1e-12f);
        }
        float lmax = 0.f;
        for(int i = gidx0; i < Bc*Gc; i += NB*NT){
            int b = i / Gc;
            float e = log1pf(expr[i]/den[b]*1e4f);
            g_e[i] = e;
            lmax = fmaxf(lmax, e);
        }
        sred[tid]=lmax; __syncthreads();
        for(int st=128; st; st>>=1){ if(tid<st) sred[tid]=fmaxf(sred[tid],sred[tid+st]); __syncthreads(); }
        if(tid==0) atomicMax(&g_umax, fflip(sred[0]));
    }
    gridbar();

    // ---------- S2: histogram + seed states ----------
    if(tid < Rc) shist32[tid] = 0;
    __syncthreads();
    {
        float maxe = funflip(g_umax);
        float step = maxe/7.0f;
        for(int i = gidx0; i < Bc*Gc; i += NB*NT){
            int b = i / Gc;
            float e = g_e[i];
            int t = (0.0f < e) ? 1 : 0;
            #pragma unroll
            for(int j=1;j<7;j++) t += ((float)j*step < e) ? 1 : 0;
            if(t>6) t=6;
            atomicAdd(&shist32[b*8+t], 1);
        }
    }
    __syncthreads();
    if(tid < Rc && shist32[tid] != 0) atomicAdd(&g_cnt[tid], shist32[tid]);
    for(int i = gidx0; i < Rc*Dc; i += NB*NT){
        int r = i >> 8, d = i & 255;
        int s = r & 7;
        g_sx[i] = (s==7) ? cls[d] : temb[s*Dc + d];
    }
    gridbar();

    // ---------- layers ----------
    for(int l=0; l<Lc; l++){
        const float* wq_l = wq + (size_t)l*Dc*Dc;  const float* bq_l = bq + l*Dc;
        const float* wk_l = wk + (size_t)l*Dc*Dc;  const float* bk_l = bk + l*Dc;
        const float* wv_l = wv + (size_t)l*Dc*Dc;  const float* bv_l = bv + l*Dc;
        const float* wo_l = wo + (size_t)l*Dc*Dc;  const float* bo_l = bo + l*Dc;
        const float* w1_l = w1 + (size_t)l*Dc*FFc; const float* b1_l = b1 + l*FFc;
        const float* w2_l = w2 + (size_t)l*FFc*Dc; const float* b2_l = b2 + l*Dc;
        const float* pr_l = projs + (size_t)l*Mc*DHc;
        const float* lg1 = ln1_g + l*Dc, *lb1 = ln1_b + l*Dc;
        const float* lg2 = ln2_g + l*Dc, *lb2 = ln2_b + l*Dc;

        // -- QKV with inline LN1: 96 tasks (w,r) --
        for(int task = bid; task < 96; task += NB){
            int r = task & 31, w = task >> 5;
            // LN of row r into srow
            float v = g_sx[(size_t)r*Dc + tid];
            sred[tid]=v; __syncthreads();
            for(int st=128; st; st>>=1){ if(tid<st) sred[tid]+=sred[tid+st]; __syncthreads(); }
            float mu = sred[0]*(1.f/256.f); __syncthreads();
            float d = v - mu;
            sred[tid]=d*d; __syncthreads();
            for(int st=128; st; st>>=1){ if(tid<st) sred[tid]+=sred[tid+st]; __syncthreads(); }
            float rstd = rsqrtf(sred[0]*(1.f/256.f) + 1e-5f); __syncthreads();
            srow[tid] = d*rstd*lg1[tid] + lb1[tid];
            __syncthreads();
            const float* W  = (w==0)?wq_l:((w==1)?wk_l:wv_l);
            const float* bb = (w==0)?bq_l:((w==1)?bk_l:bv_l);
            float* Y        = (w==0)?g_sq:((w==1)?g_sk:g_sv);
            float a0=0,a1=0,a2=0,a3=0;
            const float* wp = W + tid;
            #pragma unroll 8
            for(int k=0;k<Dc;k+=4){
                a0 += srow[k  ]*wp[(size_t)k*Dc];
                a1 += srow[k+1]*wp[(size_t)(k+1)*Dc];
                a2 += srow[k+2]*wp[(size_t)(k+2)*Dc];
                a3 += srow[k+3]*wp[(size_t)(k+3)*Dc];
            }
            Y[(size_t)r*Dc + tid] = (a0+a1)+(a2+a3) + bb[tid];
            __syncthreads();
        }
        gridbar();

        // -- attention part A: raw dd + stabilizer max (blocks 0..31) --
        if(bid < Rc){
            int b = bid>>3, h = bid&7;
            for(int i=tid;i<Mc*DHc;i+=NT) sp[i]=pr_l[i];
            { int s=warp, d=lane;
              size_t off = (size_t)(b*8+s)*Dc + h*DHc + d;
              xk[s][d]=g_sk[off]*XN_SCALE;
              xq[s][d]=g_sq[off]*XN_SCALE;
              xv[s][d]=g_sv[off]; }
            if(tid<Sc) scnt[tid] = (float)g_cnt[b*8+tid];
            __syncthreads();
            {
                float kk = xk[warp][lane]*xk[warp][lane];
                float qq = xq[warp][lane]*xq[warp][lane];
                #pragma unroll
                for(int o=16;o;o>>=1){ kk += __shfl_xor_sync(0xffffffffu,kk,o); qq += __shfl_xor_sync(0xffffffffu,qq,o); }
                if(lane==0){ dgk[warp]=0.5f*kk; dgq[warp]=0.5f*qq; }
            }
            __syncthreads();
            float mx = -3.4e38f;
            for(int i=tid;i<Sc*Mc;i+=NT){
                int s=i/Mc, m=i%Mc;
                float ddk=0.f, ddq=0.f;
                #pragma unroll
                for(int dd=0;dd<DHc;dd++){ ddk += xk[s][dd]*sp[m*DHc+dd]; ddq += xq[s][dd]*sp[m*DHc+dd]; }
                kf[s][m] = ddk;
                qf[s][m] = ddq;
                if(scnt[s] > 0.f) mx = fmaxf(mx, ddk);
            }
            sred[tid]=mx; __syncthreads();
            for(int st=128; st; st>>=1){ if(tid<st) sred[tid]=fmaxf(sred[tid],sred[tid+st]); __syncthreads(); }
            if(tid==0) atomicMax(&g_ustab[l], fflip(sred[0]));
        }
        gridbar();

        // -- attention part B (smem persisted) --
        if(bid < Rc){
            int b = bid>>3, h = bid&7;
            float stab = funflip(g_ustab[l]);
            for(int i=tid;i<Sc*Mc;i+=NT){
                int s=i/Mc, m=i%Mc;
                kf[s][m] = M_RSQRT*(expf(kf[s][m] - dgk[s] - stab) + FEPS);
            }
            __syncthreads();
            {
                float mxq=-3.4e38f;
                for(int m=lane;m<Mc;m+=32) mxq=fmaxf(mxq, qf[warp][m]);
                #pragma unroll
                for(int o=16;o;o>>=1) mxq=fmaxf(mxq,__shfl_xor_sync(0xffffffffu,mxq,o));
                for(int m=lane;m<Mc;m+=32)
                    qf[warp][m] = M_RSQRT*(expf(qf[warp][m]-dgq[warp]-mxq) + FEPS);
            }
            __syncthreads();
            for(int i=tid;i<Mc*DHc;i+=NT){
                int m=i>>5, d=i&31;
                float a=0.f;
                #pragma unroll
                for(int s=0;s<Sc;s++) a += scnt[s]*kf[s][m]*xv[s][d];
                sctx[i]=a;
            }
            for(int m=tid;m<Mc;m+=NT){
                float a=0.f;
                #pragma unroll
                for(int s=0;s<Sc;s++) a += scnt[s]*kf[s][m];
                sksum[m]=a;
            }
            __syncthreads();
            {
                float a=0.f;
                for(int m=lane;m<Mc;m+=32) a += qf[warp][m]*sksum[m];
                #pragma unroll
                for(int o=16;o;o>>=1) a += __shfl_xor_sync(0xffffffffu,a,o);
                if(lane==0) sden[warp]=a;
            }
            __syncthreads();
            {
                int s=warp, d=lane;
                float a=0.f;
                for(int m=0;m<Mc;m++) a += qf[s][m]*sctx[m*DHc+d];
                g_so[(size_t)(b*8+s)*Dc + h*DHc + d] = a/sden[s];
            }
        }
        gridbar();

        // -- Wo + residual: 32 tasks --
        for(int task = bid; task < Rc; task += NB){
            int r = task;
            srow[tid] = g_so[(size_t)r*Dc + tid];
            __syncthreads();
            float a0=0,a1=0,a2=0,a3=0;
            const float* wp = wo_l + tid;
            #pragma unroll 8
            for(int k=0;k<Dc;k+=4){
                a0 += srow[k  ]*wp[(size_t)k*Dc];
                a1 += srow[k+1]*wp[(size_t)(k+1)*Dc];
                a2 += srow[k+2]*wp[(size_t)(k+2)*Dc];
                a3 += srow[k+3]*wp[(size_t)(k+3)*Dc];
            }
            g_sx[(size_t)r*Dc + tid] += (a0+a1)+(a2+a3) + bo_l[tid];
            __syncthreads();
        }
        gridbar();

        // -- FFN1 with inline LN2 + GELU: 128 tasks (r, chunk) --
        for(int task = bid; task < 128; task += NB){
            int r = task & 31, chn = task >> 5;
            float v = g_sx[(size_t)r*Dc + tid];
            sred[tid]=v; __syncthreads();
            for(int st=128; st; st>>=1){ if(tid<st) sred[tid]+=sred[tid+st]; __syncthreads(); }
            float mu = sred[0]*(1.f/256.f); __syncthreads();
            float d = v - mu;
            sred[tid]=d*d; __syncthreads();
            for(int st=128; st; st>>=1){ if(tid<st) sred[tid]+=sred[tid+st]; __syncthreads(); }
            float rstd = rsqrtf(sred[0]*(1.f/256.f) + 1e-5f); __syncthreads();
            srow[tid] = d*rstd*lg2[tid] + lb2[tid];
            __syncthreads();
            int c = chn*256 + tid;
            float a0=0,a1=0,a2=0,a3=0;
            const float* wp = w1_l + c;
            #pragma unroll 8
            for(int k=0;k<Dc;k+=4){
                a0 += srow[k  ]*wp[(size_t)k*FFc];
                a1 += srow[k+1]*wp[(size_t)(k+1)*FFc];
                a2 += srow[k+2]*wp[(size_t)(k+2)*FFc];
                a3 += srow[k+3]*wp[(size_t)(k+3)*FFc];
            }
            g_sff[(size_t)r*FFc + c] = gelu_exact((a0+a1)+(a2+a3) + b1_l[c]);
            __syncthreads();
        }
        gridbar();

        // -- FFN2 + residual: 32 tasks, K=1024 --
        for(int task = bid; task < Rc; task += NB){
            int r = task;
            #pragma unroll
            for(int j=0;j<4;j++) srow[tid + j*256] = g_sff[(size_t)r*FFc + tid + j*256];
            __syncthreads();
            float a0=0,a1=0,a2=0,a3=0;
            const float* wp = w2_l + tid;
            #pragma unroll 8
            for(int k=0;k<FFc;k+=4){
                a0 += srow[k  ]*wp[(size_t)k*Dc];
                a1 += srow[k+1]*wp[(size_t)(k+1)*Dc];
                a2 += srow[k+2]*wp[(size_t)(k+2)*Dc];
                a3 += srow[k+3]*wp[(size_t)(k+3)*Dc];
            }
            g_sx[(size_t)r*Dc + tid] += (a0+a1)+(a2+a3) + b2_l[tid];
            __syncthreads();
        }
        gridbar();
    }

    // ---------- final projection (cls rows): 4 tasks ----------
    for(int task = bid; task < Bc; task += NB){
        int b = task;
        srow[tid] = g_sx[(size_t)(b*8+7)*Dc + tid];
        __syncthreads();
        float a0=0,a1=0,a2=0,a3=0;
        const float* wp = pw + tid;
        #pragma unroll 8
        for(int k=0;k<Dc;k+=4){
            a0 += srow[k  ]*wp[(size_t)k*Dc];
            a1 += srow[k+1]*wp[(size_t)(k+1)*Dc];
            a2 += srow[k+2]*wp[(size_t)(k+2)*Dc];
            a3 += srow[k+3]*wp[(size_t)(k+3)*Dc];
        }
        out[b*Dc + tid] = (a0+a1)+(a2+a3) + pb[tid];
        __syncthreads();
    }
}

// ---------------- launch ----------------
extern "C" void kernel_launch(void* const* d_in, const int* in_sizes, int n_in,
                              void* d_out, int out_size){
    const float* expr      = (const float*)d_in[0];
    const float* token_emb = (const float*)d_in[1];
    const float* cls_token = (const float*)d_in[2];
    const float* ln1_g     = (const float*)d_in[3];
    const float* ln1_b     = (const float*)d_in[4];
    const float* wq        = (const float*)d_in[5];
    const float* bq        = (const float*)d_in[6];
    const float* wk        = (const float*)d_in[7];
    const float* bk        = (const float*)d_in[8];
    const float* wv        = (const float*)d_in[9];
    const float* bv        = (const float*)d_in[10];
    const float* wo        = (const float*)d_in[11];
    const float* bo        = (const float*)d_in[12];
    const float* ln2_g     = (const float*)d_in[13];
    const float* ln2_b     = (const float*)d_in[14];
    const float* w1        = (const float*)d_in[15];
    const float* b1        = (const float*)d_in[16];
    const float* w2        = (const float*)d_in[17];
    const float* b2        = (const float*)d_in[18];
    const float* proj_w    = (const float*)d_in[19];
    const float* proj_b    = (const float*)d_in[20];
    const float* projs     = (const float*)d_in[21];
    float* out = (float*)d_out;

    forward_kernel<<<NB, NT>>>(expr, token_emb, cls_token,
                               ln1_g, ln1_b, wq, bq, wk, bk, wv, bv, wo, bo,
                               ln2_g, ln2_b, w1, b1, w2, b2,
                               proj_w, proj_b, projs, out);
}